// round 3
// baseline (speedup 1.0000x reference)
#include <cuda_runtime.h>
#include <cstdint>

#define N_DIM 4
#define T_DIM 12
#define V_DIM 200
#define F_DIM 64
#define VT    50      // v-rows per band (== V/N)

typedef unsigned long long u64;

// Partial column sums: [16 blocks.x][48 nt][200 w]
__device__ float g_psum[16 * 48 * 200];

// ---------------------------------------------------------------------------
// Packed fp32x2 helpers (Blackwell sm_100+)
// ---------------------------------------------------------------------------
__device__ __forceinline__ u64 padd2(u64 a, u64 b) {
    u64 r;
    asm("add.rn.f32x2 %0, %1, %2;" : "=l"(r) : "l"(a), "l"(b));
    return r;
}

__device__ __forceinline__ float2 unpack2(u64 v) {
    float2 r;
    asm("mov.b64 {%0, %1}, %2;" : "=f"(r.x), "=f"(r.y) : "l"(v));
    return r;
}

// ---------------------------------------------------------------------------
// Kernel 1: compute s, exp, scatter through the view-permutation, and emit
// per-block partial column sums for the later normalization.
//
// grid = (16, 48): blockIdx.x = np*4 + sub (np = v-band, sub = quarter of the
//                  band: 13,13,12,12 rows), blockIdx.y = nt = n*T + t.
// block = 256 threads; threads 0..199 each own one w column.
//
// Smem: y[200][64] with y = x[n,t] * a  (a >= 0 makes |dx|*a == |dy|).
// Thread keeps -y_w in 32 packed pairs in registers; loops its 12-13 v rows
// via broadcast LDS.128. 8 accumulator chains (depth 4) for ILP.
// ---------------------------------------------------------------------------
extern __shared__ unsigned char smem_raw[];

__global__ void __launch_bounds__(256)
k_compute(const float* __restrict__ x, const float* __restrict__ a,
          float* __restrict__ out) {
    const int bx  = blockIdx.x;          // 0..15
    const int nt  = blockIdx.y;          // n*T + t  (0..47)
    const int np  = bx >> 2;             // 0..3  (v band / output slab quarter)
    const int sub = bx & 3;              // 0..3  (quarter of the band)
    const int n   = nt / T_DIM;
    const int t   = nt % T_DIM;
    const int tid = threadIdx.x;

    float4* ys4 = reinterpret_cast<float4*>(smem_raw);           // 200*16 float4
    const float4* x4 = reinterpret_cast<const float4*>(
        x + (size_t)nt * V_DIM * F_DIM);
    const float4* a4 = reinterpret_cast<const float4*>(a);

    // Load + pre-scale slab: y[r][f] = x[nt][r][f] * a[f]
    for (int i = tid; i < V_DIM * (F_DIM / 4); i += 256) {
        const int fq = i & 15;           // F/4 == 16
        float4 v = x4[i];
        const float4 s = __ldg(&a4[fq]);
        v.x *= s.x; v.y *= s.y; v.z *= s.z; v.w *= s.w;
        ys4[i] = v;
    }
    __syncthreads();

    if (tid >= V_DIM) return;
    const int w = tid;

    const ulonglong2* ys2 = reinterpret_cast<const ulonglong2*>(smem_raw);

    // Register-resident negated w-row: 32 packed fp32 pairs.
    u64 ywn[32];
    const u64 NEG2 = 0x8000000080000000ULL;
    #pragma unroll
    for (int fq = 0; fq < 16; fq++) {
        ulonglong2 r = ys2[w * 16 + fq];
        ywn[2 * fq]     = r.x ^ NEG2;
        ywn[2 * fq + 1] = r.y ^ NEG2;
    }

    const u64 ABS2 = 0x7FFFFFFF7FFFFFFFULL;

    // This block's v rows within the band: 13,13,12,12 split.
    const int vstart = sub * 12 + (sub < 2 ? sub : 2);
    const int cnt    = (sub < 2) ? 13 : 12;

    // out index: ((np*T + t)*V + v')*V + w  with v' = vloc*4 + n
    float* outp = out + ((size_t)(np * T_DIM + t) * V_DIM) * V_DIM + w;
    const int vbase = np * VT + vstart;   // global row in the smem slab

    float esum = 0.0f;

    for (int l = 0; l < cnt; l++) {
        const ulonglong2* yv2 = ys2 + (size_t)(vbase + l) * 16;
        u64 acc[8];
        #pragma unroll
        for (int c = 0; c < 8; c++) acc[c] = 0ULL;

        #pragma unroll
        for (int fq = 0; fq < 16; fq++) {
            ulonglong2 q = yv2[fq];                    // broadcast LDS.128
            u64 d0 = padd2(q.x, ywn[2 * fq]) & ABS2;
            u64 d1 = padd2(q.y, ywn[2 * fq + 1]) & ABS2;
            const int c = (fq & 3) * 2;
            acc[c]     = padd2(acc[c], d0);
            acc[c + 1] = padd2(acc[c + 1], d1);
        }
        u64 r0 = padd2(padd2(acc[0], acc[2]), padd2(acc[4], acc[6]));
        u64 r1 = padd2(padd2(acc[1], acc[3]), padd2(acc[5], acc[7]));
        const float2 p = unpack2(padd2(r0, r1));
        const float e = __expf(p.x + p.y);
        esum += e;
        outp[(size_t)((vstart + l) * 4 + n) * V_DIM] = e;
    }

    g_psum[((size_t)bx * 48 + nt) * V_DIM + w] = esum;
}

// ---------------------------------------------------------------------------
// Kernel 2: reduce partial sums and rescale.
//
// grid = (48, 10): blockIdx.x = nt' (output slab), blockIdx.y = 20-row chunk.
// Each block: threads 0..199 fold 16 psum partials -> 1/sum in smem; then all
// 256 threads stream 1000 float4 (20 rows) with coalesced loads/stores.
// ---------------------------------------------------------------------------
__global__ void __launch_bounds__(256)
k_scale(float* __restrict__ out) {
    __shared__ __align__(16) float sinv[V_DIM];

    const int ntp   = blockIdx.x;            // nt' = np*T + t
    const int chunk = blockIdx.y;            // 0..9
    const int np    = ntp / T_DIM;
    const int t     = ntp % T_DIM;
    const int tid   = threadIdx.x;

    if (tid < V_DIM) {
        float s = 0.0f;
        #pragma unroll
        for (int sub = 0; sub < 4; sub++) {
            #pragma unroll
            for (int n = 0; n < 4; n++) {
                s += g_psum[((size_t)(np * 4 + sub) * 48 + (n * T_DIM + t))
                            * V_DIM + tid];
            }
        }
        sinv[tid] = 1.0f / s;
    }
    __syncthreads();

    const float4* si4 = reinterpret_cast<const float4*>(sinv);
    float4* o4 = reinterpret_cast<float4*>(out)
                 + (size_t)ntp * (V_DIM * V_DIM / 4) + (size_t)chunk * 1000;

    #pragma unroll 4
    for (int k = tid; k < 1000; k += 256) {
        float4 v = o4[k];
        const float4 iv = si4[k % 50];       // w quadrant of this float4
        v.x *= iv.x; v.y *= iv.y; v.z *= iv.z; v.w *= iv.w;
        o4[k] = v;
    }
}

// ---------------------------------------------------------------------------

extern "C" void kernel_launch(void* const* d_in, const int* in_sizes, int n_in,
                              void* d_out, int out_size) {
    const float* x = (const float*)d_in[0];
    const float* a = (const float*)d_in[1];
    // Defensive input-order check: a has exactly F=64 elements.
    if (n_in >= 2 && in_sizes[0] == F_DIM) {
        x = (const float*)d_in[1];
        a = (const float*)d_in[0];
    }
    float* out = (float*)d_out;

    const int smem_bytes = V_DIM * F_DIM * (int)sizeof(float);  // 51200 > 48K
    cudaFuncSetAttribute(k_compute, cudaFuncAttributeMaxDynamicSharedMemorySize,
                         smem_bytes);

    dim3 g1(16, N_DIM * T_DIM);      // (16, 48) = 768 blocks
    k_compute<<<g1, 256, smem_bytes>>>(x, a, out);

    dim3 g2(N_DIM * T_DIM, 10);      // (48, 10) = 480 blocks
    k_scale<<<g2, 256>>>(out);
}

// round 4
// speedup vs baseline: 1.4934x; 1.4934x over previous
#include <cuda_runtime.h>
#include <cstdint>

#define N_DIM 4
#define T_DIM 12
#define V_DIM 200
#define F_DIM 64
#define PADQ  17      // float4 per padded smem row (16 data + 1 pad) = 272B

typedef unsigned long long u64;

// Partial column sums: [np(4)][chunk(6)][nt(48)][w(200)]
__device__ float g_psum[4 * 6 * 48 * 200];

// ---------------------------------------------------------------------------
// Packed fp32x2 helpers (sm_100+)
// ---------------------------------------------------------------------------
__device__ __forceinline__ u64 padd2(u64 a, u64 b) {
    u64 r;
    asm("add.rn.f32x2 %0, %1, %2;" : "=l"(r) : "l"(a), "l"(b));
    return r;
}

__device__ __forceinline__ float2 unpack2(u64 v) {
    float2 r;
    asm("mov.b64 {%0, %1}, %2;" : "=f"(r.x), "=f"(r.y) : "l"(v));
    return r;
}

__device__ __forceinline__ float reduce4(const u64* acc) {
    u64 r = padd2(padd2(acc[0], acc[1]), padd2(acc[2], acc[3]));
    float2 p = unpack2(r);
    return p.x + p.y;
}

// ---------------------------------------------------------------------------
// Kernel 1: compute s = sum_f |y_v - y_w| (y = x*a, valid since a >= 0),
// exp, scatter through the view-permutation, emit per-(band,chunk) partial
// column sums.
//
// grid = (6, 48): blockIdx.x = chunk over the 200 (band,row) pairs
//                 (34,34,34,34,32,32), blockIdx.y = nt = n*T + t.
// block = 256 threads; threads 0..199 own one w column each.
// smem: padded y[200][68] floats (272B row stride -> conflict-free ywn setup).
// Inner loop: 2 rows/iter, 4 accumulator chains per row (16 live chains).
// ---------------------------------------------------------------------------
extern __shared__ unsigned char smem_raw[];

__global__ void __launch_bounds__(256, 2)
k_compute(const float* __restrict__ x, const float* __restrict__ a,
          float* __restrict__ out) {
    const int c   = blockIdx.x;          // 0..5
    const int nt  = blockIdx.y;          // 0..47
    const int n   = nt / T_DIM;
    const int t   = nt % T_DIM;
    const int tid = threadIdx.x;

    float4* ys4 = reinterpret_cast<float4*>(smem_raw);   // [200][17] float4
    const float4* x4 = reinterpret_cast<const float4*>(
        x + (size_t)nt * V_DIM * F_DIM);
    const float4* a4 = reinterpret_cast<const float4*>(a);

    // Load + pre-scale slab: ys[r][f] = x[nt][r][f] * a[f]  (padded rows)
    {
        const float4 ar = __ldg(&a4[tid & 15]);          // i&15 == tid&15
        for (int i = tid; i < V_DIM * 16; i += 256) {
            float4 v = x4[i];
            v.x *= ar.x; v.y *= ar.y; v.z *= ar.z; v.w *= ar.w;
            ys4[(i >> 4) * PADQ + (i & 15)] = v;
        }
    }
    __syncthreads();

    if (tid >= V_DIM) return;
    const int w = tid;

    const ulonglong2* ys2 = reinterpret_cast<const ulonglong2*>(smem_raw);

    // Register-resident negated w-row: 32 packed fp32 pairs (conflict-free:
    // padded stride 68 words spreads lanes across banks).
    u64 ywn[32];
    const u64 NEG2 = 0x8000000080000000ULL;
    #pragma unroll
    for (int fq = 0; fq < 16; fq++) {
        ulonglong2 r = ys2[w * PADQ + fq];
        ywn[2 * fq]     = r.x ^ NEG2;
        ywn[2 * fq + 1] = r.y ^ NEG2;
    }

    const u64 ABS2 = 0x7FFFFFFF7FFFFFFFULL;

    // Chunk bounds over p in [0,200): p = np*50 + vloc. All counts even.
    const int start = (c < 4) ? c * 34 : 136 + (c - 4) * 32;
    const int cnt   = (c < 4) ? 34 : 32;
    const int np0   = start / 50;
    const int np1   = (start + cnt - 1) / 50;
    const int split = (np0 + 1) * 50;    // p < split -> band np0, else np1

    float esum_lo = 0.0f, esum_hi = 0.0f;

    for (int l = 0; l < cnt; l += 2) {
        const int p0 = start + l;
        const int p1 = p0 + 1;
        const ulonglong2* r0 = ys2 + (size_t)p0 * PADQ;
        const ulonglong2* r1 = ys2 + (size_t)p1 * PADQ;

        u64 acc0[4], acc1[4];
        #pragma unroll
        for (int k = 0; k < 4; k++) { acc0[k] = 0ULL; acc1[k] = 0ULL; }

        #pragma unroll
        for (int fq = 0; fq < 16; fq++) {
            ulonglong2 q0 = r0[fq];                  // broadcast LDS.128
            ulonglong2 q1 = r1[fq];
            u64 d0a = padd2(q0.x, ywn[2 * fq])     & ABS2;
            u64 d0b = padd2(q0.y, ywn[2 * fq + 1]) & ABS2;
            u64 d1a = padd2(q1.x, ywn[2 * fq])     & ABS2;
            u64 d1b = padd2(q1.y, ywn[2 * fq + 1]) & ABS2;
            const int ci = (fq & 1) * 2;
            acc0[ci]     = padd2(acc0[ci],     d0a);
            acc0[ci + 1] = padd2(acc0[ci + 1], d0b);
            acc1[ci]     = padd2(acc1[ci],     d1a);
            acc1[ci + 1] = padd2(acc1[ci + 1], d1b);
        }

        const float e0 = __expf(reduce4(acc0));
        const float e1 = __expf(reduce4(acc1));

        // Scatter through the view permutation: slab (np,t), row vloc*4 + n.
        {
            const int npA = p0 / 50, vlA = p0 - npA * 50;
            out[(((size_t)(npA * T_DIM + t) * V_DIM) + (vlA * 4 + n)) * V_DIM + w] = e0;
            const int npB = p1 / 50, vlB = p1 - npB * 50;
            out[(((size_t)(npB * T_DIM + t) * V_DIM) + (vlB * 4 + n)) * V_DIM + w] = e1;
        }

        if (p0 < split) esum_lo += e0; else esum_hi += e0;
        if (p1 < split) esum_lo += e1; else esum_hi += e1;
    }

    // Write all 4 band partials (zeros for untouched bands -> deterministic).
    #pragma unroll
    for (int np = 0; np < 4; np++) {
        float val = 0.0f;
        if (np == np0) val = esum_lo;
        else if (np == np1) val = esum_hi;
        g_psum[(((size_t)np * 6 + c) * 48 + nt) * V_DIM + w] = val;
    }
}

// ---------------------------------------------------------------------------
// Kernel 2: reduce partials -> 1/colsum, rescale output (batched RMW).
//
// grid = (48, 10): blockIdx.x = output slab nt' = np*T + t,
//                  blockIdx.y = 1000-float4 chunk.
// ---------------------------------------------------------------------------
__global__ void __launch_bounds__(256)
k_scale(float* __restrict__ out) {
    __shared__ __align__(16) float sinv[V_DIM];

    const int ntp   = blockIdx.x;
    const int chunk = blockIdx.y;
    const int np    = ntp / T_DIM;
    const int t     = ntp % T_DIM;
    const int tid   = threadIdx.x;

    if (tid < V_DIM) {
        float s = 0.0f;
        #pragma unroll
        for (int c = 0; c < 6; c++) {
            #pragma unroll
            for (int n = 0; n < 4; n++) {
                s += g_psum[(((size_t)np * 6 + c) * 48 + (n * T_DIM + t))
                            * V_DIM + tid];
            }
        }
        sinv[tid] = 1.0f / s;
    }
    __syncthreads();

    const float4* si4 = reinterpret_cast<const float4*>(sinv);
    float4* o4 = reinterpret_cast<float4*>(out)
                 + (size_t)ntp * (V_DIM * V_DIM / 4) + (size_t)chunk * 1000;

    // Batched: all loads first (MLP=4), then scale+store.
    float4 v[4];
    int idx[4];
    #pragma unroll
    for (int j = 0; j < 4; j++) {
        idx[j] = tid + j * 256;
        if (idx[j] < 1000) v[j] = o4[idx[j]];
    }
    #pragma unroll
    for (int j = 0; j < 4; j++) {
        if (idx[j] < 1000) {
            const float4 m = si4[idx[j] % 50];
            v[j].x *= m.x; v[j].y *= m.y; v[j].z *= m.z; v[j].w *= m.w;
            o4[idx[j]] = v[j];
        }
    }
}

// ---------------------------------------------------------------------------

extern "C" void kernel_launch(void* const* d_in, const int* in_sizes, int n_in,
                              void* d_out, int out_size) {
    const float* x = (const float*)d_in[0];
    const float* a = (const float*)d_in[1];
    // Defensive input-order check: a has exactly F=64 elements.
    if (n_in >= 2 && in_sizes[0] == F_DIM) {
        x = (const float*)d_in[1];
        a = (const float*)d_in[0];
    }
    float* out = (float*)d_out;

    const int smem_bytes = V_DIM * PADQ * 4 * (int)sizeof(float);  // 54400
    cudaFuncSetAttribute(k_compute, cudaFuncAttributeMaxDynamicSharedMemorySize,
                         smem_bytes);

    dim3 g1(6, N_DIM * T_DIM);       // 288 blocks ~= 2 per SM
    k_compute<<<g1, 256, smem_bytes>>>(x, a, out);

    dim3 g2(N_DIM * T_DIM, 10);      // 480 blocks
    k_scale<<<g2, 256>>>(out);
}